// round 15
// baseline (speedup 1.0000x reference)
#include <cuda_runtime.h>
#include <math_constants.h>

#define NN 80000
#define NE 1280000
#define CAP 64                            // slots per node (P(deg>=64) ~ 1e-55)
#define NBLK_N ((NN + 255) / 256)         // 313
#define NBLK_N2 ((NN * 2) / 256)          // 625 exactly (2 threads per node)
#define AGG_BLK (NN / 8)                  // 10000 (warp per node, 64-ch only; exact)
#define BN_EPS 1e-5f
#define SLOPE 0.01f

typedef unsigned long long u64;

// ---------------- f32x2 packed-pair helpers (Blackwell FFMA2/FADD2) ----------------
__device__ __forceinline__ u64 fma2(u64 a, u64 b, u64 c) {
    u64 d;
    asm("fma.rn.f32x2 %0, %1, %2, %3;" : "=l"(d) : "l"(a), "l"(b), "l"(c));
    return d;
}
__device__ __forceinline__ u64 add2(u64 a, u64 b) {
    u64 d;
    asm("add.rn.f32x2 %0, %1, %2;" : "=l"(d) : "l"(a), "l"(b));
    return d;
}
__device__ __forceinline__ u64 pack2(float lo, float hi) {
    u64 d;
    asm("mov.b64 %0, {%1, %2};" : "=l"(d)
        : "r"(__float_as_uint(lo)), "r"(__float_as_uint(hi)));
    return d;
}
__device__ __forceinline__ float2 unpack2(u64 v) {
    unsigned lo, hi;
    asm("mov.b64 {%0, %1}, %2;" : "=r"(lo), "=r"(hi) : "l"(v));
    return make_float2(__uint_as_float(lo), __uint_as_float(hi));
}

// ---------------- persistent device scratch ----------------
__device__ int   g_cnt[NN];
__device__ int   g_srcs[NN * CAP];             // slot table
__device__ float g_dinv[NN];
__device__ __align__(16) float4 g_xs[NN];      // x * dinv, padded to float4
__device__ __align__(16) float4 g_z4[NN];      // stage0 aggregated, padded
__device__ __align__(16) float g_h[NN * 64];   // stage1 feats (dinv-scaled); stage2 reuses as float4[NN]
__device__ __align__(16) float g_y[NN * 64];
__device__ float g_part[256 * 128];
__device__ __align__(16) float g_bp[AGG_BLK * 128];   // stage1 per-block BN partials
__device__ __align__(16) float g_w1t[64 * 64];        // W1 transposed (j-major)
__device__ __align__(16) float g_w2t[3 * 64];         // W2 transposed (j-major)
__device__ float g_scale[64];
__device__ float g_shift[64];
__device__ int   g_rcount = 0;

// ---------------- build: zero counts + transpose next-stage weights ----------------
__global__ void k_zero(const float* __restrict__ w1, const float* __restrict__ w2) {
    int i = blockIdx.x * blockDim.x + threadIdx.x;
    if (i < NN) g_cnt[i] = 0;
    if (blockIdx.x == 0) {
        for (int k = threadIdx.x; k < 64 * 64; k += 256) {
            int j = k >> 6, c = k & 63;
            g_w1t[j * 64 + c] = w1[c * 64 + j];     // W1 (in,out) -> (out,in)
        }
        for (int k = threadIdx.x; k < 3 * 64; k += 256) {
            int j = k >> 6, c = k & 63;
            g_w2t[j * 64 + c] = w2[c * 3 + j];      // W2 (in,out=3) -> (3,in)
        }
    }
}

__global__ void k_fill(const int* __restrict__ src,
                       const int* __restrict__ dst) {
    int i = blockIdx.x * blockDim.x + threadIdx.x;
    if (i < NE / 4) {
        int4 s4 = ((const int4*)src)[i];
        int4 d4 = ((const int4*)dst)[i];
        #pragma unroll
        for (int k = 0; k < 4; k++) {
            int s = (&s4.x)[k], d = (&d4.x)[k];
            if ((unsigned)d < NN && (unsigned)s < NN) {
                int p = atomicAdd(&g_cnt[d], 1);
                if (p < CAP) g_srcs[d * CAP + p] = s;
            }
        }
    }
}

// dinv + pre-scaled padded input features
__global__ void k_dinvx(const float* __restrict__ x) {
    int i = blockIdx.x * blockDim.x + threadIdx.x;
    if (i < NN) {
        float dn = rsqrtf((float)g_cnt[i] + 2.0f);
        g_dinv[i] = dn;
        float4 v;
        v.x = x[i * 3 + 0] * dn;
        v.y = x[i * 3 + 1] * dn;
        v.z = x[i * 3 + 2] * dn;
        v.w = 0.f;
        g_xs[i] = v;
    }
}

__device__ __forceinline__ float warpsum(float v) {
    #pragma unroll
    for (int o = 16; o; o >>= 1) v += __shfl_xor_sync(0xffffffffu, v, o);
    return v;
}

// ---------------- 3-ch (padded float4) aggregation, 2 THREADS per node ----------------
// SRC=0: feat = g_xs (stage 0), write g_z4, no bias, no stats.
// SRC=1: feat = g_h viewed as float4[NN] (stage 2), write g_y compact 3 (+bias),
//        fused BN stats over the 3 channels (last-done block finalizes scale/shift).
// Grid is exactly NBLK_N2*256 = 2*NN threads: no early exits, __syncthreads-safe.
template <int SRC>
__global__ void k_agg4t2(const float* __restrict__ bias,
                         const float* __restrict__ gamma,
                         const float* __restrict__ beta) {
    const float4* feat = (SRC == 0) ? g_xs : (const float4*)g_h;
    int t = blockIdx.x * blockDim.x + threadIdx.x;
    int n = t >> 1, sub = t & 1;
    int warp = threadIdx.x >> 5, lane = threadIdx.x & 31;

    int deg = g_cnt[n]; if (deg > CAP) deg = CAP;
    const int4* idx = (const int4*)&g_srcs[n * CAP];
    float a0 = 0.f, a1 = 0.f, a2 = 0.f;

    int nq = deg >> 2;
    for (int j = sub; j < nq; j += 2) {
        int4 s = idx[j];
        float4 h0 = feat[s.x];
        float4 h1 = feat[s.y];
        float4 h2 = feat[s.z];
        float4 h3 = feat[s.w];
        a0 += (h0.x + h1.x) + (h2.x + h3.x);
        a1 += (h0.y + h1.y) + (h2.y + h3.y);
        a2 += (h0.z + h1.z) + (h2.z + h3.z);
    }
    for (int j = (nq << 2) + sub; j < deg; j += 2) {
        float4 h = feat[g_srcs[n * CAP + j]];
        a0 += h.x; a1 += h.y; a2 += h.z;
    }

    // combine the thread pair (adjacent lanes of the same warp)
    a0 += __shfl_xor_sync(0xffffffffu, a0, 1);
    a1 += __shfl_xor_sync(0xffffffffu, a1, 1);
    a2 += __shfl_xor_sync(0xffffffffu, a2, 1);

    float dn = g_dinv[n];
    float st = 2.f * dn;
    float4 hs = feat[n];
    float o0 = fmaf(a0, dn, st * hs.x);
    float o1 = fmaf(a1, dn, st * hs.y);
    float o2 = fmaf(a2, dn, st * hs.z);

    if constexpr (SRC == 0) {
        if (sub == 0) {
            float4 o; o.x = o0; o.y = o1; o.z = o2; o.w = 0.f;
            g_z4[n] = o;
        }
        return;
    } else {
        o0 += bias[0]; o1 += bias[1]; o2 += bias[2];
        if (sub == 0) {
            g_y[n * 3 + 0] = o0; g_y[n * 3 + 1] = o1; g_y[n * 3 + 2] = o2;
        }

        // fused BN stats: sum(3)+sumsq(3) per block, each node counted once (sub0)
        float mask = (sub == 0) ? 1.f : 0.f;
        float sv0 = mask * o0, sv1 = mask * o1, sv2 = mask * o2;
        float qv0 = mask * o0 * o0, qv1 = mask * o1 * o1, qv2 = mask * o2 * o2;
        __shared__ float ps[8][8];   // [warp][slot]; slots 0..5 used
        float w;
        w = warpsum(sv0); if (lane == 0) ps[warp][0] = w;
        w = warpsum(sv1); if (lane == 0) ps[warp][1] = w;
        w = warpsum(sv2); if (lane == 0) ps[warp][2] = w;
        w = warpsum(qv0); if (lane == 0) ps[warp][3] = w;
        w = warpsum(qv1); if (lane == 0) ps[warp][4] = w;
        w = warpsum(qv2); if (lane == 0) ps[warp][5] = w;
        __syncthreads();
        int tid = threadIdx.x;
        if (tid < 6) {
            float s = 0.f;
            #pragma unroll
            for (int ww = 0; ww < 8; ww++) s += ps[ww][tid];
            g_part[blockIdx.x * 8 + tid] = s;
        }
        __threadfence();
        __syncthreads();
        __shared__ int lastf;
        if (tid == 0) lastf = (atomicAdd(&g_rcount, 1) == NBLK_N2 - 1) ? 1 : 0;
        __syncthreads();
        if (!lastf) return;

        // final: reduce 625 blocks x 6 partials
        __shared__ float fs[256];
        int j = tid & 7, k = tid >> 3;      // j slot 0..7, k stripe 0..31
        float p = 0.f;
        if (j < 6) for (int b = k; b < NBLK_N2; b += 32) p += g_part[b * 8 + j];
        fs[tid] = p;
        __syncthreads();
        if (tid < 3) {
            float s = 0.f, q = 0.f;
            #pragma unroll
            for (int k2 = 0; k2 < 32; k2++) {
                s += fs[k2 * 8 + tid];
                q += fs[k2 * 8 + tid + 3];
            }
            float mean = s * (1.0f / NN);
            float var = fmaxf(q * (1.0f / NN) - mean * mean, 0.f);
            float sc = gamma[tid] * rsqrtf(var + BN_EPS);
            g_scale[tid] = sc;
            g_shift[tid] = beta[tid] - mean * sc;
        }
        if (tid == 0) g_rcount = 0;
    }
}

// ---------------- BN finalize (last-done block, NPART=256) ----------------
template <int C>
__device__ __forceinline__ void bn_finalize(const float* __restrict__ gamma,
                                            const float* __restrict__ beta,
                                            float* ss, float* sq) {
    int tid = threadIdx.x;
    __threadfence();
    __syncthreads();
    __shared__ int lastf;
    if (tid == 0) lastf = (atomicAdd(&g_rcount, 1) == 255) ? 1 : 0;
    __syncthreads();
    if (!lastf) return;

    int fc = tid & 63;
    int fr = tid >> 6;
    float fs = 0.f, fq = 0.f;
    if (fc < C) {
        for (int b = fr; b < 256; b += 4) {
            fs += g_part[b * 128 + fc];
            fq += g_part[b * 128 + 64 + fc];
        }
    }
    ss[tid] = fs; sq[tid] = fq;
    __syncthreads();
    if (fr == 0 && fc < C) {
        for (int k = 1; k < 4; k++) { fs += ss[k * 64 + fc]; fq += sq[k * 64 + fc]; }
        float mean = fs * (1.0f / NN);
        float var = fmaxf(fq * (1.0f / NN) - mean * mean, 0.f);
        float sc = gamma[fc] * rsqrtf(var + BN_EPS);
        g_scale[fc] = sc;
        g_shift[fc] = beta[fc] - mean * sc;
    }
    if (tid == 0) g_rcount = 0;
}

// ---------------- stage0: y = z@W0 + b0 fused with BN stats ----------------
__global__ void k_mmred(const float* __restrict__ W, const float* __restrict__ bias,
                        const float* __restrict__ gamma, const float* __restrict__ beta) {
    int c = threadIdx.x & 63;
    int r = threadIdx.x >> 6;    // 0..3
    float w0 = W[c], w1 = W[64 + c], w2 = W[128 + c], bv = bias[c];
    float s = 0.f, q = 0.f;
    for (int n = blockIdx.x * 4 + r; n < NN; n += 1024) {
        float4 z = g_z4[n];
        float y = fmaf(z.x, w0, fmaf(z.y, w1, fmaf(z.z, w2, bv)));
        s += y; q = fmaf(y, y, q);
        g_y[n * 64 + c] = y;
    }
    __shared__ float ss[256], sq[256];
    ss[threadIdx.x] = s; sq[threadIdx.x] = q;
    __syncthreads();
    if (r == 0) {
        for (int k = 1; k < 4; k++) { s += ss[k * 64 + c]; q += sq[k * 64 + c]; }
        g_part[blockIdx.x * 128 + c]      = s;
        g_part[blockIdx.x * 128 + 64 + c] = q;
    }
    bn_finalize<64>(gamma, beta, ss, sq);
}

// ---------------- stage1: 64-ch aggregation (ADD2) + per-block BN partials ----------------
__global__ void k_agg64(const float* __restrict__ bias) {
    __shared__ __align__(16) float ssm[8 * 64];
    __shared__ __align__(16) float sqm[8 * 64];
    int tid = threadIdx.x;
    int gw = (blockIdx.x * blockDim.x + tid) >> 5;   // grid exact: gw < NN always
    int lane = tid & 31;
    int warp = tid >> 5;
    int half = lane >> 4;          // 0/1: which edge of the pair
    int ql = lane & 15;            // float4 slot within row

    int beg = gw * CAP;
    int deg = g_cnt[gw]; if (deg > CAP) deg = CAP;
    int end = beg + deg;
    u64 acA = pack2(0.f, 0.f), acB = pack2(0.f, 0.f);

    int e = beg;
    for (; e + 8 <= end; e += 8) {
        int s0 = g_srcs[e + half];
        int s1 = g_srcs[e + 2 + half];
        int s2 = g_srcs[e + 4 + half];
        int s3 = g_srcs[e + 6 + half];
        ulonglong2 h0 = ((const ulonglong2*)&g_h[s0 * 64])[ql];
        ulonglong2 h1 = ((const ulonglong2*)&g_h[s1 * 64])[ql];
        ulonglong2 h2 = ((const ulonglong2*)&g_h[s2 * 64])[ql];
        ulonglong2 h3 = ((const ulonglong2*)&g_h[s3 * 64])[ql];
        acA = add2(acA, add2(add2(h0.x, h1.x), add2(h2.x, h3.x)));
        acB = add2(acB, add2(add2(h0.y, h1.y), add2(h2.y, h3.y)));
    }
    for (; e + 2 <= end; e += 2) {
        int s = g_srcs[e + half];
        ulonglong2 h = ((const ulonglong2*)&g_h[s * 64])[ql];
        acA = add2(acA, h.x);
        acB = add2(acB, h.y);
    }
    if (e < end && half == 0) {
        int s = g_srcs[e];
        ulonglong2 h = ((const ulonglong2*)&g_h[s * 64])[ql];
        acA = add2(acA, h.x);
        acB = add2(acB, h.y);
    }

    float2 pA = unpack2(acA), pB = unpack2(acB);
    float ax = pA.x, ay = pA.y, az = pB.x, aw = pB.y;

    // combine the two half-warps
    ax += __shfl_xor_sync(0xffffffffu, ax, 16);
    ay += __shfl_xor_sync(0xffffffffu, ay, 16);
    az += __shfl_xor_sync(0xffffffffu, az, 16);
    aw += __shfl_xor_sync(0xffffffffu, aw, 16);

    if (half == 0) {
        float dn = g_dinv[gw];
        float st = 2.f * dn;
        float4 hs = ((const float4*)&g_h[gw * 64])[ql];
        float4 bv = ((const float4*)bias)[ql];
        float4 o;
        o.x = fmaf(ax, dn, fmaf(st, hs.x, bv.x));
        o.y = fmaf(ay, dn, fmaf(st, hs.y, bv.y));
        o.z = fmaf(az, dn, fmaf(st, hs.z, bv.z));
        o.w = fmaf(aw, dn, fmaf(st, hs.w, bv.w));
        ((float4*)&g_y[gw * 64])[ql] = o;
        ((float4*)&ssm[warp * 64])[ql] = o;
        float4 q2;
        q2.x = o.x * o.x; q2.y = o.y * o.y; q2.z = o.z * o.z; q2.w = o.w * o.w;
        ((float4*)&sqm[warp * 64])[ql] = q2;
    }
    __syncthreads();
    if (tid < 64) {
        float s = 0.f, q = 0.f;
        #pragma unroll
        for (int w = 0; w < 8; w++) { s += ssm[w * 64 + tid]; q += sqm[w * 64 + tid]; }
        g_bp[blockIdx.x * 128 + tid]      = s;
        g_bp[blockIdx.x * 128 + 64 + tid] = q;
    }
}

// ---------------- stage1 stats: reduce g_bp -> scale/shift ----------------
__global__ void k_finstats(const float* __restrict__ gamma, const float* __restrict__ beta) {
    int c = threadIdx.x & 63;
    int r = threadIdx.x >> 6;    // 0..3
    float s = 0.f, q = 0.f;
    for (int b = blockIdx.x * 4 + r; b < AGG_BLK; b += 1024) {
        s += g_bp[b * 128 + c];
        q += g_bp[b * 128 + 64 + c];
    }
    __shared__ float ss[256], sq[256];
    ss[threadIdx.x] = s; sq[threadIdx.x] = q;
    __syncthreads();
    if (r == 0) {
        for (int k = 1; k < 4; k++) { s += ss[k * 64 + c]; q += sq[k * 64 + c]; }
        g_part[blockIdx.x * 128 + c]      = s;
        g_part[blockIdx.x * 128 + 64 + c] = q;
    }
    bn_finalize<64>(gamma, beta, ss, sq);
}

// ---------------- fused: BN apply + pool + lrelu + linear + lrelu + next W (f32x2) ----------------
// COUT2==64 -> write rows to g_h[N,64] (uses g_w1t); COUT2==3 -> padded float4 rows (uses g_w2t)
template <int PK, int PP, int COUT2>
__global__ __launch_bounds__(128) void k_postmm(const float* __restrict__ lw,
                                                const float* __restrict__ lb) {
    __shared__ __align__(16) float lws[64 * 64];
    __shared__ __align__(16) float w2s[COUT2 * 64];
    __shared__ float lbs[64], sc[64], sh[64];
    const float* w2src = (COUT2 == 64) ? g_w1t : g_w2t;
    int tid = threadIdx.x;
    for (int i = tid; i < 64 * 64; i += 128) lws[i] = lw[i];
    for (int i = tid; i < COUT2 * 64; i += 128) w2s[i] = w2src[i];
    if (tid < 64) { lbs[tid] = lb[tid]; sc[tid] = g_scale[tid]; sh[tid] = g_shift[tid]; }
    __syncthreads();
    int n = blockIdx.x * 128 + tid;
    if (n >= NN) return;
    float dn = g_dinv[n];

    float t[64];
    {
        const float4* yv = (const float4*)&g_y[n * 64];
        #pragma unroll
        for (int i = 0; i < 16; i++) {
            float4 v = yv[i];
            t[4 * i]     = fmaf(v.x, sc[4 * i],     sh[4 * i]);
            t[4 * i + 1] = fmaf(v.y, sc[4 * i + 1], sh[4 * i + 1]);
            t[4 * i + 2] = fmaf(v.z, sc[4 * i + 2], sh[4 * i + 2]);
            t[4 * i + 3] = fmaf(v.w, sc[4 * i + 3], sh[4 * i + 3]);
        }
    }

    // pool + leaky, packed into f32x2 pairs over c
    u64 m2[32];
    #pragma unroll
    for (int cp = 0; cp < 32; cp++) {
        float mv[2];
        #pragma unroll
        for (int k = 0; k < 2; k++) {
            int c = 2 * cp + k;
            int lo = c - PP; if (lo < 0) lo = 0;
            int hi = c - PP + PK - 1; if (hi > 63) hi = 63;
            float mx = t[lo];
            #pragma unroll
            for (int d = 0; d < PK; d++) {
                int idx = c - PP + d;
                if (idx > lo && idx <= hi) mx = fmaxf(mx, t[idx]);
            }
            mv[k] = (mx >= 0.f) ? mx : SLOPE * mx;
        }
        m2[cp] = pack2(mv[0], mv[1]);
    }

    // lin1: r[j] = leaky(lb[j] + sum_c m[c]*lw[j][c]) via f32x2 pairs
    u64 r2[32];
    #pragma unroll 2
    for (int j0 = 0; j0 < 64; j0 += 2) {
        float rv[2];
        #pragma unroll
        for (int jj = 0; jj < 2; jj++) {
            int j = j0 + jj;
            u64 acc = pack2(lbs[j], 0.f);
            const ulonglong2* row = (const ulonglong2*)&lws[j * 64];
            #pragma unroll
            for (int q = 0; q < 16; q++) {
                ulonglong2 w = row[q];
                acc = fma2(m2[2 * q], w.x, acc);
                acc = fma2(m2[2 * q + 1], w.y, acc);
            }
            float2 p = unpack2(acc);
            float a = p.x + p.y;
            rv[jj] = (a >= 0.f) ? a : SLOPE * a;
        }
        r2[j0 >> 1] = pack2(rv[0], rv[1]);
    }

    // mm2: out[j] = (sum_c r[c] * Wt[j][c]) * dn via f32x2 pairs (Wt pre-transposed)
    if constexpr (COUT2 == 64) {
        #pragma unroll 1
        for (int j0 = 0; j0 < 64; j0 += 4) {
            float o[4];
            #pragma unroll
            for (int jj = 0; jj < 4; jj++) {
                int j = j0 + jj;
                u64 acc = pack2(0.f, 0.f);
                const ulonglong2* row = (const ulonglong2*)&w2s[j * 64];
                #pragma unroll
                for (int q = 0; q < 16; q++) {
                    ulonglong2 w = row[q];
                    acc = fma2(r2[2 * q], w.x, acc);
                    acc = fma2(r2[2 * q + 1], w.y, acc);
                }
                float2 p = unpack2(acc);
                o[jj] = (p.x + p.y) * dn;
            }
            float4 ov; ov.x = o[0]; ov.y = o[1]; ov.z = o[2]; ov.w = o[3];
            *(float4*)&g_h[n * 64 + j0] = ov;
        }
    } else {
        float o[3];
        #pragma unroll
        for (int j = 0; j < 3; j++) {
            u64 acc = pack2(0.f, 0.f);
            const ulonglong2* row = (const ulonglong2*)&w2s[j * 64];
            #pragma unroll
            for (int q = 0; q < 16; q++) {
                ulonglong2 w = row[q];
                acc = fma2(r2[2 * q], w.x, acc);
                acc = fma2(r2[2 * q + 1], w.y, acc);
            }
            float2 p = unpack2(acc);
            o[j] = (p.x + p.y) * dn;
        }
        float4 ov; ov.x = o[0]; ov.y = o[1]; ov.z = o[2]; ov.w = 0.f;
        ((float4*)g_h)[n] = ov;     // padded float4 row for stage-2 gather
    }
}

// ---------------- final stage post (C=3) -> d_out ----------------
__global__ void k_post3(const float* __restrict__ lw, const float* __restrict__ lb,
                        float* __restrict__ outp) {
    __shared__ float lws[9], lbs[3], sc[3], sh[3];
    if (threadIdx.x < 9) lws[threadIdx.x] = lw[threadIdx.x];
    if (threadIdx.x < 3) {
        lbs[threadIdx.x] = lb[threadIdx.x];
        sc[threadIdx.x]  = g_scale[threadIdx.x];
        sh[threadIdx.x]  = g_shift[threadIdx.x];
    }
    __syncthreads();
    int n = blockIdx.x * blockDim.x + threadIdx.x;
    if (n >= NN) return;

    float t0 = fmaf(g_y[n * 3 + 0], sc[0], sh[0]);
    float t1 = fmaf(g_y[n * 3 + 1], sc[1], sh[1]);
    float t2 = fmaf(g_y[n * 3 + 2], sc[2], sh[2]);
    float m0 = fmaxf(t0, t1);
    float m1 = fmaxf(m0, t2);
    float m2 = fmaxf(t1, t2);
    m0 = (m0 >= 0.f) ? m0 : SLOPE * m0;
    m1 = (m1 >= 0.f) ? m1 : SLOPE * m1;
    m2 = (m2 >= 0.f) ? m2 : SLOPE * m2;
    #pragma unroll
    for (int j = 0; j < 3; j++) {
        float a = lbs[j];
        a = fmaf(m0, lws[j * 3 + 0], a);
        a = fmaf(m1, lws[j * 3 + 1], a);
        a = fmaf(m2, lws[j * 3 + 2], a);
        outp[n * 3 + j] = (a >= 0.f) ? a : SLOPE * a;
    }
}

// ---------------- launch ----------------
extern "C" void kernel_launch(void* const* d_in, const int* in_sizes, int n_in,
                              void* d_out, int out_size) {
    const float* x   = (const float*)d_in[0];
    const int*   ei  = (const int*)d_in[1];
    const int*   src = ei;
    const int*   dst = ei + NE;
    const float *w0 = (const float*)d_in[2],  *b0 = (const float*)d_in[3];
    const float *g0 = (const float*)d_in[4],  *bb0 = (const float*)d_in[5];
    const float *lw0 = (const float*)d_in[6], *lb0 = (const float*)d_in[7];
    const float *w1 = (const float*)d_in[8],  *b1 = (const float*)d_in[9];
    const float *g1 = (const float*)d_in[10], *bb1 = (const float*)d_in[11];
    const float *lw1 = (const float*)d_in[12], *lb1 = (const float*)d_in[13];
    const float *w2 = (const float*)d_in[14], *b2 = (const float*)d_in[15];
    const float *g2 = (const float*)d_in[16], *bb2 = (const float*)d_in[17];
    const float *lw2 = (const float*)d_in[18], *lb2 = (const float*)d_in[19];
    float* out = (float*)d_out;

    // build (+ weight transposes in block 0)
    k_zero<<<NBLK_N, 256>>>(w1, w2);
    k_fill<<<(NE / 4 + 255) / 256, 256>>>(src, dst);
    k_dinvx<<<NBLK_N, 256>>>(x);

    // stage 0
    k_agg4t2<0><<<NBLK_N2, 256>>>(nullptr, nullptr, nullptr);     // g_xs -> g_z4
    k_mmred<<<256, 256>>>(w0, b0, g0, bb0);                       // g_y = z@W0+b0, BN stats
    k_postmm<3, 1, 64><<<(NN + 127) / 128, 128>>>(lw0, lb0);      // -> g_h (dinv-scaled)

    // stage 1
    k_agg64<<<AGG_BLK, 256>>>(b1);                                // -> g_y + g_bp partials
    k_finstats<<<256, 256>>>(g1, bb1);                            // g_bp -> scale/shift
    k_postmm<5, 2, 3><<<(NN + 127) / 128, 128>>>(lw1, lb1);       // -> g_h as float4[NN]

    // stage 2 (fused BN stats — arm (b) isolated test)
    k_agg4t2<1><<<NBLK_N2, 256>>>(b2, g2, bb2);                   // -> g_y[N,3] + scale/shift
    k_post3<<<NBLK_N, 256>>>(lw2, lb2, out);
}

// round 16
// speedup vs baseline: 1.0356x; 1.0356x over previous
#include <cuda_runtime.h>
#include <cuda_fp16.h>
#include <math_constants.h>

#define NN 80000
#define NE 1280000
#define CAP 64                            // slots per node (P(deg>=64) ~ 1e-55)
#define NBLK_N ((NN + 255) / 256)         // 313
#define NBLK_N2 ((NN * 2) / 256)          // 625 exactly (2 threads per node)
#define AGG_BLK (NN / 8)                  // 10000 (warp per node, 64-ch only; exact)
#define BN_EPS 1e-5f
#define SLOPE 0.01f

typedef unsigned long long u64;

// ---------------- f32x2 packed-pair helpers (Blackwell FFMA2) ----------------
__device__ __forceinline__ u64 fma2(u64 a, u64 b, u64 c) {
    u64 d;
    asm("fma.rn.f32x2 %0, %1, %2, %3;" : "=l"(d) : "l"(a), "l"(b), "l"(c));
    return d;
}
__device__ __forceinline__ u64 pack2(float lo, float hi) {
    u64 d;
    asm("mov.b64 %0, {%1, %2};" : "=l"(d)
        : "r"(__float_as_uint(lo)), "r"(__float_as_uint(hi)));
    return d;
}
__device__ __forceinline__ float2 unpack2(u64 v) {
    unsigned lo, hi;
    asm("mov.b64 {%0, %1}, %2;" : "=r"(lo), "=r"(hi) : "l"(v));
    return make_float2(__uint_as_float(lo), __uint_as_float(hi));
}

// ---------------- persistent device scratch ----------------
__device__ int   g_cnt[NN];
__device__ int   g_srcs[NN * CAP];             // slot table
__device__ float g_dinv[NN];
__device__ __align__(16) float4 g_xs[NN];      // x * dinv, padded to float4
__device__ __align__(16) float4 g_z4[NN];      // stage0 aggregated, padded
__device__ __align__(16) __half g_hh[NN * 64]; // stage1 feats (dinv-scaled), fp16
__device__ __align__(16) float g_h[NN * 64];   // stage2 feats as float4[NN] padded rows
__device__ __align__(16) float g_y[NN * 64];
__device__ float g_part[256 * 128];
__device__ __align__(16) float g_bp[AGG_BLK * 128];   // stage1 per-block BN partials
__device__ __align__(16) float g_w1t[64 * 64];        // W1 transposed (j-major)
__device__ __align__(16) float g_w2t[3 * 64];         // W2 transposed (j-major)
__device__ float g_scale[64];
__device__ float g_shift[64];
__device__ int   g_rcount = 0;

// ---------------- build: zero counts + transpose next-stage weights ----------------
__global__ void k_zero(const float* __restrict__ w1, const float* __restrict__ w2) {
    int i = blockIdx.x * blockDim.x + threadIdx.x;
    if (i < NN) g_cnt[i] = 0;
    if (blockIdx.x == 0) {
        for (int k = threadIdx.x; k < 64 * 64; k += 256) {
            int j = k >> 6, c = k & 63;
            g_w1t[j * 64 + c] = w1[c * 64 + j];     // W1 (in,out) -> (out,in)
        }
        for (int k = threadIdx.x; k < 3 * 64; k += 256) {
            int j = k >> 6, c = k & 63;
            g_w2t[j * 64 + c] = w2[c * 3 + j];      // W2 (in,out=3) -> (3,in)
        }
    }
}

__global__ void k_fill(const int* __restrict__ src,
                       const int* __restrict__ dst) {
    int i = blockIdx.x * blockDim.x + threadIdx.x;
    if (i < NE / 4) {
        int4 s4 = ((const int4*)src)[i];
        int4 d4 = ((const int4*)dst)[i];
        #pragma unroll
        for (int k = 0; k < 4; k++) {
            int s = (&s4.x)[k], d = (&d4.x)[k];
            if ((unsigned)d < NN && (unsigned)s < NN) {
                int p = atomicAdd(&g_cnt[d], 1);
                if (p < CAP) g_srcs[d * CAP + p] = s;
            }
        }
    }
}

// dinv + pre-scaled padded input features
__global__ void k_dinvx(const float* __restrict__ x) {
    int i = blockIdx.x * blockDim.x + threadIdx.x;
    if (i < NN) {
        float dn = rsqrtf((float)g_cnt[i] + 2.0f);
        g_dinv[i] = dn;
        float4 v;
        v.x = x[i * 3 + 0] * dn;
        v.y = x[i * 3 + 1] * dn;
        v.z = x[i * 3 + 2] * dn;
        v.w = 0.f;
        g_xs[i] = v;
    }
}

// ---------------- 3-ch (padded float4) aggregation, 2 THREADS per node ----------------
// SRC=0: feat = g_xs (stage 0), write g_z4, no bias.
// SRC=1: feat = g_h viewed as float4[NN] (stage 2), write g_y compact 3, + bias.
template <int SRC>
__global__ void k_agg4t2(const float* __restrict__ bias) {
    const float4* feat = (SRC == 0) ? g_xs : (const float4*)g_h;
    int t = blockIdx.x * blockDim.x + threadIdx.x;
    int n = t >> 1, sub = t & 1;
    if (n >= NN) return;

    int deg = g_cnt[n]; if (deg > CAP) deg = CAP;
    const int4* idx = (const int4*)&g_srcs[n * CAP];
    float a0 = 0.f, a1 = 0.f, a2 = 0.f;

    int nq = deg >> 2;
    for (int j = sub; j < nq; j += 2) {
        int4 s = idx[j];
        float4 h0 = feat[s.x];
        float4 h1 = feat[s.y];
        float4 h2 = feat[s.z];
        float4 h3 = feat[s.w];
        a0 += (h0.x + h1.x) + (h2.x + h3.x);
        a1 += (h0.y + h1.y) + (h2.y + h3.y);
        a2 += (h0.z + h1.z) + (h2.z + h3.z);
    }
    for (int j = (nq << 2) + sub; j < deg; j += 2) {
        float4 h = feat[g_srcs[n * CAP + j]];
        a0 += h.x; a1 += h.y; a2 += h.z;
    }

    // combine the thread pair (adjacent lanes of the same warp)
    a0 += __shfl_xor_sync(0xffffffffu, a0, 1);
    a1 += __shfl_xor_sync(0xffffffffu, a1, 1);
    a2 += __shfl_xor_sync(0xffffffffu, a2, 1);

    if (sub == 0) {
        float dn = g_dinv[n];
        float st = 2.f * dn;
        float4 hs = feat[n];
        float o0 = fmaf(a0, dn, st * hs.x);
        float o1 = fmaf(a1, dn, st * hs.y);
        float o2 = fmaf(a2, dn, st * hs.z);
        if (SRC == 1) {
            g_y[n * 3 + 0] = o0 + bias[0];
            g_y[n * 3 + 1] = o1 + bias[1];
            g_y[n * 3 + 2] = o2 + bias[2];
        } else {
            float4 o; o.x = o0; o.y = o1; o.z = o2; o.w = 0.f;
            g_z4[n] = o;
        }
    }
}

// ---------------- BN finalize (last-done block, NPART=256) ----------------
template <int C>
__device__ __forceinline__ void bn_finalize(const float* __restrict__ gamma,
                                            const float* __restrict__ beta,
                                            float* ss, float* sq) {
    int tid = threadIdx.x;
    __threadfence();
    __syncthreads();
    __shared__ int lastf;
    if (tid == 0) lastf = (atomicAdd(&g_rcount, 1) == 255) ? 1 : 0;
    __syncthreads();
    if (!lastf) return;

    int fc = tid & 63;
    int fr = tid >> 6;
    float fs = 0.f, fq = 0.f;
    if (fc < C) {
        for (int b = fr; b < 256; b += 4) {
            fs += g_part[b * 128 + fc];
            fq += g_part[b * 128 + 64 + fc];
        }
    }
    ss[tid] = fs; sq[tid] = fq;
    __syncthreads();
    if (fr == 0 && fc < C) {
        for (int k = 1; k < 4; k++) { fs += ss[k * 64 + fc]; fq += sq[k * 64 + fc]; }
        float mean = fs * (1.0f / NN);
        float var = fmaxf(fq * (1.0f / NN) - mean * mean, 0.f);
        float sc = gamma[fc] * rsqrtf(var + BN_EPS);
        g_scale[fc] = sc;
        g_shift[fc] = beta[fc] - mean * sc;
    }
    if (tid == 0) g_rcount = 0;
}

// ---------------- stage0: y = z@W0 + b0 fused with BN stats ----------------
__global__ void k_mmred(const float* __restrict__ W, const float* __restrict__ bias,
                        const float* __restrict__ gamma, const float* __restrict__ beta) {
    int c = threadIdx.x & 63;
    int r = threadIdx.x >> 6;    // 0..3
    float w0 = W[c], w1 = W[64 + c], w2 = W[128 + c], bv = bias[c];
    float s = 0.f, q = 0.f;
    for (int n = blockIdx.x * 4 + r; n < NN; n += 1024) {
        float4 z = g_z4[n];
        float y = fmaf(z.x, w0, fmaf(z.y, w1, fmaf(z.z, w2, bv)));
        s += y; q = fmaf(y, y, q);
        g_y[n * 64 + c] = y;
    }
    __shared__ float ss[256], sq[256];
    ss[threadIdx.x] = s; sq[threadIdx.x] = q;
    __syncthreads();
    if (r == 0) {
        for (int k = 1; k < 4; k++) { s += ss[k * 64 + c]; q += sq[k * 64 + c]; }
        g_part[blockIdx.x * 128 + c]      = s;
        g_part[blockIdx.x * 128 + 64 + c] = q;
    }
    bn_finalize<64>(gamma, beta, ss, sq);
}

// ---------------- standalone BN stats over g_y (stage 2, C=3) ----------------
template <int C>
__global__ void k_redstats(const float* __restrict__ gamma, const float* __restrict__ beta) {
    constexpr int CP = (C > 4) ? C : 4;
    constexpr int RPB = 256 / CP;
    int c = threadIdx.x % CP;
    int r = threadIdx.x / CP;
    float s = 0.f, q = 0.f;
    if (c < C) {
        for (int n = blockIdx.x * RPB + r; n < NN; n += 256 * RPB) {
            float v = g_y[n * C + c];
            s += v; q = fmaf(v, v, q);
        }
    }
    __shared__ float ss[256], sq[256];
    ss[threadIdx.x] = s; sq[threadIdx.x] = q;
    __syncthreads();
    if (r == 0 && c < C) {
        for (int k = 1; k < RPB; k++) { s += ss[k * CP + c]; q += sq[k * CP + c]; }
        g_part[blockIdx.x * 128 + c]      = s;
        g_part[blockIdx.x * 128 + 64 + c] = q;
    }
    bn_finalize<C>(gamma, beta, ss, sq);
}

// ---------------- stage1: 64-ch fp16 aggregation + per-block BN partials ----------------
// lane ql covers channels [4ql, 4ql+4) = one uint2 (4 halves) per row
__global__ void k_agg64(const float* __restrict__ bias) {
    __shared__ __align__(16) float ssm[8 * 64];
    __shared__ __align__(16) float sqm[8 * 64];
    int tid = threadIdx.x;
    int gw = (blockIdx.x * blockDim.x + tid) >> 5;   // grid exact: gw < NN always
    int lane = tid & 31;
    int warp = tid >> 5;
    int half = lane >> 4;          // 0/1: which edge of the pair
    int ql = lane & 15;            // 4-channel slot within row

    int beg = gw * CAP;
    int deg = g_cnt[gw]; if (deg > CAP) deg = CAP;
    int end = beg + deg;
    float ax = 0.f, ay = 0.f, az = 0.f, aw = 0.f;

    int e = beg;
    for (; e + 8 <= end; e += 8) {
        int s0 = g_srcs[e + half];
        int s1 = g_srcs[e + 2 + half];
        int s2 = g_srcs[e + 4 + half];
        int s3 = g_srcs[e + 6 + half];
        uint2 v0 = ((const uint2*)&g_hh[s0 * 64])[ql];
        uint2 v1 = ((const uint2*)&g_hh[s1 * 64])[ql];
        uint2 v2 = ((const uint2*)&g_hh[s2 * 64])[ql];
        uint2 v3 = ((const uint2*)&g_hh[s3 * 64])[ql];
        float2 l0 = __half22float2(*(const __half2*)&v0.x), h0 = __half22float2(*(const __half2*)&v0.y);
        float2 l1 = __half22float2(*(const __half2*)&v1.x), h1 = __half22float2(*(const __half2*)&v1.y);
        float2 l2 = __half22float2(*(const __half2*)&v2.x), h2 = __half22float2(*(const __half2*)&v2.y);
        float2 l3 = __half22float2(*(const __half2*)&v3.x), h3 = __half22float2(*(const __half2*)&v3.y);
        ax += (l0.x + l1.x) + (l2.x + l3.x);
        ay += (l0.y + l1.y) + (l2.y + l3.y);
        az += (h0.x + h1.x) + (h2.x + h3.x);
        aw += (h0.y + h1.y) + (h2.y + h3.y);
    }
    for (; e + 2 <= end; e += 2) {
        int s = g_srcs[e + half];
        uint2 v = ((const uint2*)&g_hh[s * 64])[ql];
        float2 l = __half22float2(*(const __half2*)&v.x), h = __half22float2(*(const __half2*)&v.y);
        ax += l.x; ay += l.y; az += h.x; aw += h.y;
    }
    if (e < end && half == 0) {
        int s = g_srcs[e];
        uint2 v = ((const uint2*)&g_hh[s * 64])[ql];
        float2 l = __half22float2(*(const __half2*)&v.x), h = __half22float2(*(const __half2*)&v.y);
        ax += l.x; ay += l.y; az += h.x; aw += h.y;
    }

    // combine the two half-warps
    ax += __shfl_xor_sync(0xffffffffu, ax, 16);
    ay += __shfl_xor_sync(0xffffffffu, ay, 16);
    az += __shfl_xor_sync(0xffffffffu, az, 16);
    aw += __shfl_xor_sync(0xffffffffu, aw, 16);

    if (half == 0) {
        float dn = g_dinv[gw];
        float st = 2.f * dn;
        uint2 hv = ((const uint2*)&g_hh[gw * 64])[ql];
        float2 hl = __half22float2(*(const __half2*)&hv.x);
        float2 hh = __half22float2(*(const __half2*)&hv.y);
        float4 bv = ((const float4*)bias)[ql];
        float4 o;
        o.x = fmaf(ax, dn, fmaf(st, hl.x, bv.x));
        o.y = fmaf(ay, dn, fmaf(st, hl.y, bv.y));
        o.z = fmaf(az, dn, fmaf(st, hh.x, bv.z));
        o.w = fmaf(aw, dn, fmaf(st, hh.y, bv.w));
        ((float4*)&g_y[gw * 64])[ql] = o;
        ((float4*)&ssm[warp * 64])[ql] = o;
        float4 q2;
        q2.x = o.x * o.x; q2.y = o.y * o.y; q2.z = o.z * o.z; q2.w = o.w * o.w;
        ((float4*)&sqm[warp * 64])[ql] = q2;
    }
    __syncthreads();
    if (tid < 64) {
        float s = 0.f, q = 0.f;
        #pragma unroll
        for (int w = 0; w < 8; w++) { s += ssm[w * 64 + tid]; q += sqm[w * 64 + tid]; }
        g_bp[blockIdx.x * 128 + tid]      = s;
        g_bp[blockIdx.x * 128 + 64 + tid] = q;
    }
}

// ---------------- stage1 stats: reduce g_bp -> scale/shift ----------------
__global__ void k_finstats(const float* __restrict__ gamma, const float* __restrict__ beta) {
    int c = threadIdx.x & 63;
    int r = threadIdx.x >> 6;    // 0..3
    float s = 0.f, q = 0.f;
    for (int b = blockIdx.x * 4 + r; b < AGG_BLK; b += 1024) {
        s += g_bp[b * 128 + c];
        q += g_bp[b * 128 + 64 + c];
    }
    __shared__ float ss[256], sq[256];
    ss[threadIdx.x] = s; sq[threadIdx.x] = q;
    __syncthreads();
    if (r == 0) {
        for (int k = 1; k < 4; k++) { s += ss[k * 64 + c]; q += sq[k * 64 + c]; }
        g_part[blockIdx.x * 128 + c]      = s;
        g_part[blockIdx.x * 128 + 64 + c] = q;
    }
    bn_finalize<64>(gamma, beta, ss, sq);
}

// ---------------- fused: BN apply + pool + lrelu + linear + lrelu + next W (f32x2) ----------------
// COUT2==64 -> write fp16 rows to g_hh (uses g_w1t); COUT2==3 -> padded float4 rows to g_h (uses g_w2t)
template <int PK, int PP, int COUT2>
__global__ __launch_bounds__(128) void k_postmm(const float* __restrict__ lw,
                                                const float* __restrict__ lb) {
    __shared__ __align__(16) float lws[64 * 64];
    __shared__ __align__(16) float w2s[COUT2 * 64];
    __shared__ float lbs[64], sc[64], sh[64];
    const float* w2src = (COUT2 == 64) ? g_w1t : g_w2t;
    int tid = threadIdx.x;
    for (int i = tid; i < 64 * 64; i += 128) lws[i] = lw[i];
    for (int i = tid; i < COUT2 * 64; i += 128) w2s[i] = w2src[i];
    if (tid < 64) { lbs[tid] = lb[tid]; sc[tid] = g_scale[tid]; sh[tid] = g_shift[tid]; }
    __syncthreads();
    int n = blockIdx.x * 128 + tid;
    if (n >= NN) return;
    float dn = g_dinv[n];

    float t[64];
    {
        const float4* yv = (const float4*)&g_y[n * 64];
        #pragma unroll
        for (int i = 0; i < 16; i++) {
            float4 v = yv[i];
            t[4 * i]     = fmaf(v.x, sc[4 * i],     sh[4 * i]);
            t[4 * i + 1] = fmaf(v.y, sc[4 * i + 1], sh[4 * i + 1]);
            t[4 * i + 2] = fmaf(v.z, sc[4 * i + 2], sh[4 * i + 2]);
            t[4 * i + 3] = fmaf(v.w, sc[4 * i + 3], sh[4 * i + 3]);
        }
    }

    // pool + leaky, packed into f32x2 pairs over c
    u64 m2[32];
    #pragma unroll
    for (int cp = 0; cp < 32; cp++) {
        float mv[2];
        #pragma unroll
        for (int k = 0; k < 2; k++) {
            int c = 2 * cp + k;
            int lo = c - PP; if (lo < 0) lo = 0;
            int hi = c - PP + PK - 1; if (hi > 63) hi = 63;
            float mx = t[lo];
            #pragma unroll
            for (int d = 0; d < PK; d++) {
                int idx = c - PP + d;
                if (idx > lo && idx <= hi) mx = fmaxf(mx, t[idx]);
            }
            mv[k] = (mx >= 0.f) ? mx : SLOPE * mx;
        }
        m2[cp] = pack2(mv[0], mv[1]);
    }

    // lin1: r[j] = leaky(lb[j] + sum_c m[c]*lw[j][c]) via f32x2 pairs
    u64 r2[32];
    #pragma unroll 2
    for (int j0 = 0; j0 < 64; j0 += 2) {
        float rv[2];
        #pragma unroll
        for (int jj = 0; jj < 2; jj++) {
            int j = j0 + jj;
            u64 acc = pack2(lbs[j], 0.f);
            const ulonglong2* row = (const ulonglong2*)&lws[j * 64];
            #pragma unroll
            for (int q = 0; q < 16; q++) {
                ulonglong2 w = row[q];
                acc = fma2(m2[2 * q], w.x, acc);
                acc = fma2(m2[2 * q + 1], w.y, acc);
            }
            float2 p = unpack2(acc);
            float a = p.x + p.y;
            rv[jj] = (a >= 0.f) ? a : SLOPE * a;
        }
        r2[j0 >> 1] = pack2(rv[0], rv[1]);
    }

    // mm2: out[j] = (sum_c r[c] * Wt[j][c]) * dn via f32x2 pairs (Wt pre-transposed)
    if constexpr (COUT2 == 64) {
        #pragma unroll 1
        for (int j0 = 0; j0 < 64; j0 += 4) {
            float o[4];
            #pragma unroll
            for (int jj = 0; jj < 4; jj++) {
                int j = j0 + jj;
                u64 acc = pack2(0.f, 0.f);
                const ulonglong2* row = (const ulonglong2*)&w2s[j * 64];
                #pragma unroll
                for (int q = 0; q < 16; q++) {
                    ulonglong2 w = row[q];
                    acc = fma2(r2[2 * q], w.x, acc);
                    acc = fma2(r2[2 * q + 1], w.y, acc);
                }
                float2 p = unpack2(acc);
                o[jj] = (p.x + p.y) * dn;
            }
            __half2 ha = __floats2half2_rn(o[0], o[1]);
            __half2 hb = __floats2half2_rn(o[2], o[3]);
            uint2 st;
            st.x = *(unsigned*)&ha; st.y = *(unsigned*)&hb;
            *(uint2*)&g_hh[n * 64 + j0] = st;
        }
    } else {
        float o[3];
        #pragma unroll
        for (int j = 0; j < 3; j++) {
            u64 acc = pack2(0.f, 0.f);
            const ulonglong2* row = (const ulonglong2*)&w2s[j * 64];
            #pragma unroll
            for (int q = 0; q < 16; q++) {
                ulonglong2 w = row[q];
                acc = fma2(r2[2 * q], w.x, acc);
                acc = fma2(r2[2 * q + 1], w.y, acc);
            }
            float2 p = unpack2(acc);
            o[j] = (p.x + p.y) * dn;
        }
        float4 ov; ov.x = o[0]; ov.y = o[1]; ov.z = o[2]; ov.w = 0.f;
        ((float4*)g_h)[n] = ov;     // padded float4 row for stage-2 gather
    }
}

// ---------------- final stage post (C=3) -> d_out ----------------
__global__ void k_post3(const float* __restrict__ lw, const float* __restrict__ lb,
                        float* __restrict__ outp) {
    __shared__ float lws[9], lbs[3], sc[3], sh[3];
    if (threadIdx.x < 9) lws[threadIdx.x] = lw[threadIdx.x];
    if (threadIdx.x < 3) {
        lbs[threadIdx.x] = lb[threadIdx.x];
        sc[threadIdx.x]  = g_scale[threadIdx.x];
        sh[threadIdx.x]  = g_shift[threadIdx.x];
    }
    __syncthreads();
    int n = blockIdx.x * blockDim.x + threadIdx.x;
    if (n >= NN) return;

    float t0 = fmaf(g_y[n * 3 + 0], sc[0], sh[0]);
    float t1 = fmaf(g_y[n * 3 + 1], sc[1], sh[1]);
    float t2 = fmaf(g_y[n * 3 + 2], sc[2], sh[2]);
    float m0 = fmaxf(t0, t1);
    float m1 = fmaxf(m0, t2);
    float m2 = fmaxf(t1, t2);
    m0 = (m0 >= 0.f) ? m0 : SLOPE * m0;
    m1 = (m1 >= 0.f) ? m1 : SLOPE * m1;
    m2 = (m2 >= 0.f) ? m2 : SLOPE * m2;
    #pragma unroll
    for (int j = 0; j < 3; j++) {
        float a = lbs[j];
        a = fmaf(m0, lws[j * 3 + 0], a);
        a = fmaf(m1, lws[j * 3 + 1], a);
        a = fmaf(m2, lws[j * 3 + 2], a);
        outp[n * 3 + j] = (a >= 0.f) ? a : SLOPE * a;
    }
}

// ---------------- launch ----------------
extern "C" void kernel_launch(void* const* d_in, const int* in_sizes, int n_in,
                              void* d_out, int out_size) {
    const float* x   = (const float*)d_in[0];
    const int*   ei  = (const int*)d_in[1];
    const int*   src = ei;
    const int*   dst = ei + NE;
    const float *w0 = (const float*)d_in[2],  *b0 = (const float*)d_in[3];
    const float *g0 = (const float*)d_in[4],  *bb0 = (const float*)d_in[5];
    const float *lw0 = (const float*)d_in[6], *lb0 = (const float*)d_in[7];
    const float *w1 = (const float*)d_in[8],  *b1 = (const float*)d_in[9];
    const float *g1 = (const float*)d_in[10], *bb1 = (const float*)d_in[11];
    const float *lw1 = (const float*)d_in[12], *lb1 = (const float*)d_in[13];
    const float *w2 = (const float*)d_in[14], *b2 = (const float*)d_in[15];
    const float *g2 = (const float*)d_in[16], *bb2 = (const float*)d_in[17];
    const float *lw2 = (const float*)d_in[18], *lb2 = (const float*)d_in[19];
    float* out = (float*)d_out;

    // build (+ weight transposes in block 0)
    k_zero<<<NBLK_N, 256>>>(w1, w2);
    k_fill<<<(NE / 4 + 255) / 256, 256>>>(src, dst);
    k_dinvx<<<NBLK_N, 256>>>(x);

    // stage 0
    k_agg4t2<0><<<NBLK_N2, 256>>>(nullptr);                       // g_xs -> g_z4
    k_mmred<<<256, 256>>>(w0, b0, g0, bb0);                       // g_y = z@W0+b0, BN stats
    k_postmm<3, 1, 64><<<(NN + 127) / 128, 128>>>(lw0, lb0);      // -> g_hh (fp16, dinv-scaled)

    // stage 1
    k_agg64<<<AGG_BLK, 256>>>(b1);                                // -> g_y + g_bp partials
    k_finstats<<<256, 256>>>(g1, bb1);                            // g_bp -> scale/shift
    k_postmm<5, 2, 3><<<(NN + 127) / 128, 128>>>(lw1, lb1);       // -> g_h as float4[NN]

    // stage 2
    k_agg4t2<1><<<NBLK_N2, 256>>>(b2);                            // -> g_y[N,3]
    k_redstats<3><<<256, 256>>>(g2, bb2);
    k_post3<<<NBLK_N, 256>>>(lw2, lb2, out);
}

// round 17
// speedup vs baseline: 1.0876x; 1.0503x over previous
#include <cuda_runtime.h>
#include <cuda_fp16.h>
#include <math_constants.h>

#define NN 80000
#define NE 1280000
#define CAP 64                            // slots per node (P(deg>=64) ~ 1e-55)
#define NBLK_N ((NN + 255) / 256)         // 313
#define NBLK_N2 ((NN * 2) / 256)          // 625 exactly (2 threads per node)
#define AGG_BLK (NN / 8)                  // 10000 (warp per node, 64-ch only; exact)
#define BN_EPS 1e-5f
#define SLOPE 0.01f

typedef unsigned long long u64;

// ---------------- f32x2 packed-pair helpers (Blackwell FFMA2) ----------------
__device__ __forceinline__ u64 fma2(u64 a, u64 b, u64 c) {
    u64 d;
    asm("fma.rn.f32x2 %0, %1, %2, %3;" : "=l"(d) : "l"(a), "l"(b), "l"(c));
    return d;
}
__device__ __forceinline__ u64 pack2(float lo, float hi) {
    u64 d;
    asm("mov.b64 %0, {%1, %2};" : "=l"(d)
        : "r"(__float_as_uint(lo)), "r"(__float_as_uint(hi)));
    return d;
}
__device__ __forceinline__ float2 unpack2(u64 v) {
    unsigned lo, hi;
    asm("mov.b64 {%0, %1}, %2;" : "=r"(lo), "=r"(hi) : "l"(v));
    return make_float2(__uint_as_float(lo), __uint_as_float(hi));
}

// ---------------- persistent device scratch ----------------
__device__ int   g_cnt[NN];
__device__ int   g_srcs[NN * CAP];             // slot table
__device__ float g_dinv[NN];
__device__ __align__(16) float4 g_xs[NN];      // x * dinv, padded to float4
__device__ __align__(16) float4 g_z4[NN];      // stage0 aggregated, padded
__device__ __align__(16) __half g_hh[NN * 64]; // stage1 feats (dinv-scaled), fp16
__device__ __align__(16) float g_h[NN * 64];   // stage2 feats as float4[NN] padded rows
__device__ __align__(16) float g_y[NN * 64];
__device__ float g_part[256 * 128];
__device__ __align__(16) float g_bp[AGG_BLK * 128];   // stage1 per-block BN partials
__device__ __align__(16) float g_w1t[64 * 64];        // W1 transposed (j-major)
__device__ __align__(16) float g_w2t[3 * 64];         // W2 transposed (j-major)
__device__ float g_scale[64];
__device__ float g_shift[64];
__device__ int   g_rcount = 0;

// ---------------- build: zero counts + transpose next-stage weights ----------------
__global__ void k_zero(const float* __restrict__ w1, const float* __restrict__ w2) {
    int i = blockIdx.x * blockDim.x + threadIdx.x;
    if (i < NN) g_cnt[i] = 0;
    if (blockIdx.x == 0) {
        for (int k = threadIdx.x; k < 64 * 64; k += 256) {
            int j = k >> 6, c = k & 63;
            g_w1t[j * 64 + c] = w1[c * 64 + j];     // W1 (in,out) -> (out,in)
        }
        for (int k = threadIdx.x; k < 3 * 64; k += 256) {
            int j = k >> 6, c = k & 63;
            g_w2t[j * 64 + c] = w2[c * 3 + j];      // W2 (in,out=3) -> (3,in)
        }
    }
}

__global__ void k_fill(const int* __restrict__ src,
                       const int* __restrict__ dst) {
    int i = blockIdx.x * blockDim.x + threadIdx.x;
    if (i < NE / 4) {
        int4 s4 = ((const int4*)src)[i];
        int4 d4 = ((const int4*)dst)[i];
        #pragma unroll
        for (int k = 0; k < 4; k++) {
            int s = (&s4.x)[k], d = (&d4.x)[k];
            if ((unsigned)d < NN && (unsigned)s < NN) {
                int p = atomicAdd(&g_cnt[d], 1);
                if (p < CAP) g_srcs[d * CAP + p] = s;
            }
        }
    }
}

// dinv + pre-scaled padded input features
__global__ void k_dinvx(const float* __restrict__ x) {
    int i = blockIdx.x * blockDim.x + threadIdx.x;
    if (i < NN) {
        float dn = rsqrtf((float)g_cnt[i] + 2.0f);
        g_dinv[i] = dn;
        float4 v;
        v.x = x[i * 3 + 0] * dn;
        v.y = x[i * 3 + 1] * dn;
        v.z = x[i * 3 + 2] * dn;
        v.w = 0.f;
        g_xs[i] = v;
    }
}

__device__ __forceinline__ float warpsum(float v) {
    #pragma unroll
    for (int o = 16; o; o >>= 1) v += __shfl_xor_sync(0xffffffffu, v, o);
    return v;
}

// ---------------- 3-ch (padded float4) aggregation, 2 THREADS per node ----------------
// SRC=0: feat = g_xs (stage 0), write g_z4, no bias, no stats.
// SRC=1: feat = g_h viewed as float4[NN] (stage 2), write g_y compact 3 (+bias),
//        fused BN stats (last-done block finalizes scale/shift). Grid exact, sync-safe.
template <int SRC>
__global__ void k_agg4t2(const float* __restrict__ bias,
                         const float* __restrict__ gamma,
                         const float* __restrict__ beta) {
    const float4* feat = (SRC == 0) ? g_xs : (const float4*)g_h;
    int t = blockIdx.x * blockDim.x + threadIdx.x;
    int n = t >> 1, sub = t & 1;
    int warp = threadIdx.x >> 5, lane = threadIdx.x & 31;

    int deg = g_cnt[n]; if (deg > CAP) deg = CAP;
    const int4* idx = (const int4*)&g_srcs[n * CAP];
    float a0 = 0.f, a1 = 0.f, a2 = 0.f;

    int nq = deg >> 2;
    for (int j = sub; j < nq; j += 2) {
        int4 s = idx[j];
        float4 h0 = feat[s.x];
        float4 h1 = feat[s.y];
        float4 h2 = feat[s.z];
        float4 h3 = feat[s.w];
        a0 += (h0.x + h1.x) + (h2.x + h3.x);
        a1 += (h0.y + h1.y) + (h2.y + h3.y);
        a2 += (h0.z + h1.z) + (h2.z + h3.z);
    }
    for (int j = (nq << 2) + sub; j < deg; j += 2) {
        float4 h = feat[g_srcs[n * CAP + j]];
        a0 += h.x; a1 += h.y; a2 += h.z;
    }

    a0 += __shfl_xor_sync(0xffffffffu, a0, 1);
    a1 += __shfl_xor_sync(0xffffffffu, a1, 1);
    a2 += __shfl_xor_sync(0xffffffffu, a2, 1);

    float dn = g_dinv[n];
    float st = 2.f * dn;
    float4 hs = feat[n];
    float o0 = fmaf(a0, dn, st * hs.x);
    float o1 = fmaf(a1, dn, st * hs.y);
    float o2 = fmaf(a2, dn, st * hs.z);

    if constexpr (SRC == 0) {
        if (sub == 0) {
            float4 o; o.x = o0; o.y = o1; o.z = o2; o.w = 0.f;
            g_z4[n] = o;
        }
        return;
    } else {
        o0 += bias[0]; o1 += bias[1]; o2 += bias[2];
        if (sub == 0) {
            g_y[n * 3 + 0] = o0; g_y[n * 3 + 1] = o1; g_y[n * 3 + 2] = o2;
        }

        // fused BN stats (each node counted once via sub0)
        float mask = (sub == 0) ? 1.f : 0.f;
        float sv0 = mask * o0, sv1 = mask * o1, sv2 = mask * o2;
        float qv0 = mask * o0 * o0, qv1 = mask * o1 * o1, qv2 = mask * o2 * o2;
        __shared__ float ps[8][8];
        float w;
        w = warpsum(sv0); if (lane == 0) ps[warp][0] = w;
        w = warpsum(sv1); if (lane == 0) ps[warp][1] = w;
        w = warpsum(sv2); if (lane == 0) ps[warp][2] = w;
        w = warpsum(qv0); if (lane == 0) ps[warp][3] = w;
        w = warpsum(qv1); if (lane == 0) ps[warp][4] = w;
        w = warpsum(qv2); if (lane == 0) ps[warp][5] = w;
        __syncthreads();
        int tid = threadIdx.x;
        if (tid < 6) {
            float s = 0.f;
            #pragma unroll
            for (int ww = 0; ww < 8; ww++) s += ps[ww][tid];
            g_part[blockIdx.x * 8 + tid] = s;
        }
        __threadfence();
        __syncthreads();
        __shared__ int lastf;
        if (tid == 0) lastf = (atomicAdd(&g_rcount, 1) == NBLK_N2 - 1) ? 1 : 0;
        __syncthreads();
        if (!lastf) return;

        __shared__ float fs[256];
        int j = tid & 7, k = tid >> 3;
        float p = 0.f;
        if (j < 6) for (int b = k; b < NBLK_N2; b += 32) p += g_part[b * 8 + j];
        fs[tid] = p;
        __syncthreads();
        if (tid < 3) {
            float s = 0.f, q = 0.f;
            #pragma unroll
            for (int k2 = 0; k2 < 32; k2++) {
                s += fs[k2 * 8 + tid];
                q += fs[k2 * 8 + tid + 3];
            }
            float mean = s * (1.0f / NN);
            float var = fmaxf(q * (1.0f / NN) - mean * mean, 0.f);
            float sc = gamma[tid] * rsqrtf(var + BN_EPS);
            g_scale[tid] = sc;
            g_shift[tid] = beta[tid] - mean * sc;
        }
        if (tid == 0) g_rcount = 0;
    }
}

// ---------------- BN finalize (last-done block, NPART=256) ----------------
template <int C>
__device__ __forceinline__ void bn_finalize(const float* __restrict__ gamma,
                                            const float* __restrict__ beta,
                                            float* ss, float* sq) {
    int tid = threadIdx.x;
    __threadfence();
    __syncthreads();
    __shared__ int lastf;
    if (tid == 0) lastf = (atomicAdd(&g_rcount, 1) == 255) ? 1 : 0;
    __syncthreads();
    if (!lastf) return;

    int fc = tid & 63;
    int fr = tid >> 6;
    float fs = 0.f, fq = 0.f;
    if (fc < C) {
        for (int b = fr; b < 256; b += 4) {
            fs += g_part[b * 128 + fc];
            fq += g_part[b * 128 + 64 + fc];
        }
    }
    ss[tid] = fs; sq[tid] = fq;
    __syncthreads();
    if (fr == 0 && fc < C) {
        for (int k = 1; k < 4; k++) { fs += ss[k * 64 + fc]; fq += sq[k * 64 + fc]; }
        float mean = fs * (1.0f / NN);
        float var = fmaxf(fq * (1.0f / NN) - mean * mean, 0.f);
        float sc = gamma[fc] * rsqrtf(var + BN_EPS);
        g_scale[fc] = sc;
        g_shift[fc] = beta[fc] - mean * sc;
    }
    if (tid == 0) g_rcount = 0;
}

// ---------------- stage0: BN stats of y = z@W0 + b0 (no y store) ----------------
__global__ void k_mmred(const float* __restrict__ W, const float* __restrict__ bias,
                        const float* __restrict__ gamma, const float* __restrict__ beta) {
    int c = threadIdx.x & 63;
    int r = threadIdx.x >> 6;    // 0..3
    float w0 = W[c], w1 = W[64 + c], w2 = W[128 + c], bv = bias[c];
    float s = 0.f, q = 0.f;
    for (int n = blockIdx.x * 4 + r; n < NN; n += 1024) {
        float4 z = g_z4[n];
        float y = fmaf(z.x, w0, fmaf(z.y, w1, fmaf(z.z, w2, bv)));
        s += y; q = fmaf(y, y, q);
    }
    __shared__ float ss[256], sq[256];
    ss[threadIdx.x] = s; sq[threadIdx.x] = q;
    __syncthreads();
    if (r == 0) {
        for (int k = 1; k < 4; k++) { s += ss[k * 64 + c]; q += sq[k * 64 + c]; }
        g_part[blockIdx.x * 128 + c]      = s;
        g_part[blockIdx.x * 128 + 64 + c] = q;
    }
    bn_finalize<64>(gamma, beta, ss, sq);
}

// ---------------- stage1: 64-ch fp16 aggregation + per-block BN partials ----------------
__global__ void k_agg64(const float* __restrict__ bias) {
    __shared__ __align__(16) float ssm[8 * 64];
    __shared__ __align__(16) float sqm[8 * 64];
    int tid = threadIdx.x;
    int gw = (blockIdx.x * blockDim.x + tid) >> 5;   // grid exact: gw < NN always
    int lane = tid & 31;
    int warp = tid >> 5;
    int half = lane >> 4;          // 0/1: which edge of the pair
    int ql = lane & 15;            // 4-channel slot within row

    int beg = gw * CAP;
    int deg = g_cnt[gw]; if (deg > CAP) deg = CAP;
    int end = beg + deg;
    float ax = 0.f, ay = 0.f, az = 0.f, aw = 0.f;

    int e = beg;
    for (; e + 8 <= end; e += 8) {
        int s0 = g_srcs[e + half];
        int s1 = g_srcs[e + 2 + half];
        int s2 = g_srcs[e + 4 + half];
        int s3 = g_srcs[e + 6 + half];
        uint2 v0 = ((const uint2*)&g_hh[s0 * 64])[ql];
        uint2 v1 = ((const uint2*)&g_hh[s1 * 64])[ql];
        uint2 v2 = ((const uint2*)&g_hh[s2 * 64])[ql];
        uint2 v3 = ((const uint2*)&g_hh[s3 * 64])[ql];
        float2 l0 = __half22float2(*(const __half2*)&v0.x), h0 = __half22float2(*(const __half2*)&v0.y);
        float2 l1 = __half22float2(*(const __half2*)&v1.x), h1 = __half22float2(*(const __half2*)&v1.y);
        float2 l2 = __half22float2(*(const __half2*)&v2.x), h2 = __half22float2(*(const __half2*)&v2.y);
        float2 l3 = __half22float2(*(const __half2*)&v3.x), h3 = __half22float2(*(const __half2*)&v3.y);
        ax += (l0.x + l1.x) + (l2.x + l3.x);
        ay += (l0.y + l1.y) + (l2.y + l3.y);
        az += (h0.x + h1.x) + (h2.x + h3.x);
        aw += (h0.y + h1.y) + (h2.y + h3.y);
    }
    for (; e + 2 <= end; e += 2) {
        int s = g_srcs[e + half];
        uint2 v = ((const uint2*)&g_hh[s * 64])[ql];
        float2 l = __half22float2(*(const __half2*)&v.x), h = __half22float2(*(const __half2*)&v.y);
        ax += l.x; ay += l.y; az += h.x; aw += h.y;
    }
    if (e < end && half == 0) {
        int s = g_srcs[e];
        uint2 v = ((const uint2*)&g_hh[s * 64])[ql];
        float2 l = __half22float2(*(const __half2*)&v.x), h = __half22float2(*(const __half2*)&v.y);
        ax += l.x; ay += l.y; az += h.x; aw += h.y;
    }

    ax += __shfl_xor_sync(0xffffffffu, ax, 16);
    ay += __shfl_xor_sync(0xffffffffu, ay, 16);
    az += __shfl_xor_sync(0xffffffffu, az, 16);
    aw += __shfl_xor_sync(0xffffffffu, aw, 16);

    if (half == 0) {
        float dn = g_dinv[gw];
        float st = 2.f * dn;
        uint2 hv = ((const uint2*)&g_hh[gw * 64])[ql];
        float2 hl = __half22float2(*(const __half2*)&hv.x);
        float2 hh = __half22float2(*(const __half2*)&hv.y);
        float4 bv = ((const float4*)bias)[ql];
        float4 o;
        o.x = fmaf(ax, dn, fmaf(st, hl.x, bv.x));
        o.y = fmaf(ay, dn, fmaf(st, hl.y, bv.y));
        o.z = fmaf(az, dn, fmaf(st, hh.x, bv.z));
        o.w = fmaf(aw, dn, fmaf(st, hh.y, bv.w));
        ((float4*)&g_y[gw * 64])[ql] = o;
        ((float4*)&ssm[warp * 64])[ql] = o;
        float4 q2;
        q2.x = o.x * o.x; q2.y = o.y * o.y; q2.z = o.z * o.z; q2.w = o.w * o.w;
        ((float4*)&sqm[warp * 64])[ql] = q2;
    }
    __syncthreads();
    if (tid < 64) {
        float s = 0.f, q = 0.f;
        #pragma unroll
        for (int w = 0; w < 8; w++) { s += ssm[w * 64 + tid]; q += sqm[w * 64 + tid]; }
        g_bp[blockIdx.x * 128 + tid]      = s;
        g_bp[blockIdx.x * 128 + 64 + tid] = q;
    }
}

// ---------------- stage1 stats: reduce g_bp -> scale/shift ----------------
__global__ void k_finstats(const float* __restrict__ gamma, const float* __restrict__ beta) {
    int c = threadIdx.x & 63;
    int r = threadIdx.x >> 6;    // 0..3
    float s = 0.f, q = 0.f;
    for (int b = blockIdx.x * 4 + r; b < AGG_BLK; b += 1024) {
        s += g_bp[b * 128 + c];
        q += g_bp[b * 128 + 64 + c];
    }
    __shared__ float ss[256], sq[256];
    ss[threadIdx.x] = s; sq[threadIdx.x] = q;
    __syncthreads();
    if (r == 0) {
        for (int k = 1; k < 4; k++) { s += ss[k * 64 + c]; q += sq[k * 64 + c]; }
        g_part[blockIdx.x * 128 + c]      = s;
        g_part[blockIdx.x * 128 + 64 + c] = q;
    }
    bn_finalize<64>(gamma, beta, ss, sq);
}

// ---------------- fused: [y recompute or load] + BN + pool + lrelu + linear + lrelu + next W ----------------
// FROMZ: y recomputed from g_z4 (stage 0). else: y from g_y (stage 1).
// COUT2==64 -> fp16 rows to g_hh (g_w1t); COUT2==3 -> padded float4 rows to g_h (g_w2t)
template <int PK, int PP, int COUT2, bool FROMZ>
__global__ __launch_bounds__(128) void k_postmm(const float* __restrict__ lw,
                                                const float* __restrict__ lb,
                                                const float* __restrict__ W0,
                                                const float* __restrict__ b0) {
    __shared__ __align__(16) float lws[64 * 64];
    __shared__ __align__(16) float w2s[COUT2 * 64];
    __shared__ float lbs[64], sc[64], sh[64];
    __shared__ float w0s[192], b0s[64];
    const float* w2src = (COUT2 == 64) ? g_w1t : g_w2t;
    int tid = threadIdx.x;
    for (int i = tid; i < 64 * 64; i += 128) lws[i] = lw[i];
    for (int i = tid; i < COUT2 * 64; i += 128) w2s[i] = w2src[i];
    if (FROMZ) {
        for (int i = tid; i < 192; i += 128) w0s[i] = W0[i];
        if (tid < 64) b0s[tid] = b0[tid];
    }
    if (tid < 64) { lbs[tid] = lb[tid]; sc[tid] = g_scale[tid]; sh[tid] = g_shift[tid]; }
    __syncthreads();
    int n = blockIdx.x * 128 + tid;
    if (n >= NN) return;
    float dn = g_dinv[n];

    float t[64];
    if constexpr (FROMZ) {
        float4 z = g_z4[n];
        #pragma unroll 8
        for (int j = 0; j < 64; j++) {
            float y = fmaf(z.x, w0s[j], fmaf(z.y, w0s[64 + j], fmaf(z.z, w0s[128 + j], b0s[j])));
            t[j] = fmaf(y, sc[j], sh[j]);
        }
    } else {
        const float4* yv = (const float4*)&g_y[n * 64];
        #pragma unroll
        for (int i = 0; i < 16; i++) {
            float4 v = yv[i];
            t[4 * i]     = fmaf(v.x, sc[4 * i],     sh[4 * i]);
            t[4 * i + 1] = fmaf(v.y, sc[4 * i + 1], sh[4 * i + 1]);
            t[4 * i + 2] = fmaf(v.z, sc[4 * i + 2], sh[4 * i + 2]);
            t[4 * i + 3] = fmaf(v.w, sc[4 * i + 3], sh[4 * i + 3]);
        }
    }

    // pool + leaky, packed into f32x2 pairs over c
    u64 m2[32];
    #pragma unroll
    for (int cp = 0; cp < 32; cp++) {
        float mv[2];
        #pragma unroll
        for (int k = 0; k < 2; k++) {
            int c = 2 * cp + k;
            int lo = c - PP; if (lo < 0) lo = 0;
            int hi = c - PP + PK - 1; if (hi > 63) hi = 63;
            float mx = t[lo];
            #pragma unroll
            for (int d = 0; d < PK; d++) {
                int idx = c - PP + d;
                if (idx > lo && idx <= hi) mx = fmaxf(mx, t[idx]);
            }
            mv[k] = (mx >= 0.f) ? mx : SLOPE * mx;
        }
        m2[cp] = pack2(mv[0], mv[1]);
    }

    // lin1: r[j] = leaky(lb[j] + sum_c m[c]*lw[j][c]) via f32x2 pairs
    u64 r2[32];
    #pragma unroll 2
    for (int j0 = 0; j0 < 64; j0 += 2) {
        float rv[2];
        #pragma unroll
        for (int jj = 0; jj < 2; jj++) {
            int j = j0 + jj;
            u64 acc = pack2(lbs[j], 0.f);
            const ulonglong2* row = (const ulonglong2*)&lws[j * 64];
            #pragma unroll
            for (int q = 0; q < 16; q++) {
                ulonglong2 w = row[q];
                acc = fma2(m2[2 * q], w.x, acc);
                acc = fma2(m2[2 * q + 1], w.y, acc);
            }
            float2 p = unpack2(acc);
            float a = p.x + p.y;
            rv[jj] = (a >= 0.f) ? a : SLOPE * a;
        }
        r2[j0 >> 1] = pack2(rv[0], rv[1]);
    }

    // mm2: out[j] = (sum_c r[c] * Wt[j][c]) * dn via f32x2 pairs
    if constexpr (COUT2 == 64) {
        #pragma unroll 1
        for (int j0 = 0; j0 < 64; j0 += 4) {
            float o[4];
            #pragma unroll
            for (int jj = 0; jj < 4; jj++) {
                int j = j0 + jj;
                u64 acc = pack2(0.f, 0.f);
                const ulonglong2* row = (const ulonglong2*)&w2s[j * 64];
                #pragma unroll
                for (int q = 0; q < 16; q++) {
                    ulonglong2 w = row[q];
                    acc = fma2(r2[2 * q], w.x, acc);
                    acc = fma2(r2[2 * q + 1], w.y, acc);
                }
                float2 p = unpack2(acc);
                o[jj] = (p.x + p.y) * dn;
            }
            __half2 ha = __floats2half2_rn(o[0], o[1]);
            __half2 hb = __floats2half2_rn(o[2], o[3]);
            uint2 st;
            st.x = *(unsigned*)&ha; st.y = *(unsigned*)&hb;
            *(uint2*)&g_hh[n * 64 + j0] = st;
        }
    } else {
        float o[3];
        #pragma unroll
        for (int j = 0; j < 3; j++) {
            u64 acc = pack2(0.f, 0.f);
            const ulonglong2* row = (const ulonglong2*)&w2s[j * 64];
            #pragma unroll
            for (int q = 0; q < 16; q++) {
                ulonglong2 w = row[q];
                acc = fma2(r2[2 * q], w.x, acc);
                acc = fma2(r2[2 * q + 1], w.y, acc);
            }
            float2 p = unpack2(acc);
            o[j] = (p.x + p.y) * dn;
        }
        float4 ov; ov.x = o[0]; ov.y = o[1]; ov.z = o[2]; ov.w = 0.f;
        ((float4*)g_h)[n] = ov;     // padded float4 row for stage-2 gather
    }
}

// ---------------- final stage post (C=3) -> d_out ----------------
__global__ void k_post3(const float* __restrict__ lw, const float* __restrict__ lb,
                        float* __restrict__ outp) {
    __shared__ float lws[9], lbs[3], sc[3], sh[3];
    if (threadIdx.x < 9) lws[threadIdx.x] = lw[threadIdx.x];
    if (threadIdx.x < 3) {
        lbs[threadIdx.x] = lb[threadIdx.x];
        sc[threadIdx.x]  = g_scale[threadIdx.x];
        sh[threadIdx.x]  = g_shift[threadIdx.x];
    }
    __syncthreads();
    int n = blockIdx.x * blockDim.x + threadIdx.x;
    if (n >= NN) return;

    float t0 = fmaf(g_y[n * 3 + 0], sc[0], sh[0]);
    float t1 = fmaf(g_y[n * 3 + 1], sc[1], sh[1]);
    float t2 = fmaf(g_y[n * 3 + 2], sc[2], sh[2]);
    float m0 = fmaxf(t0, t1);
    float m1 = fmaxf(m0, t2);
    float m2 = fmaxf(t1, t2);
    m0 = (m0 >= 0.f) ? m0 : SLOPE * m0;
    m1 = (m1 >= 0.f) ? m1 : SLOPE * m1;
    m2 = (m2 >= 0.f) ? m2 : SLOPE * m2;
    #pragma unroll
    for (int j = 0; j < 3; j++) {
        float a = lbs[j];
        a = fmaf(m0, lws[j * 3 + 0], a);
        a = fmaf(m1, lws[j * 3 + 1], a);
        a = fmaf(m2, lws[j * 3 + 2], a);
        outp[n * 3 + j] = (a >= 0.f) ? a : SLOPE * a;
    }
}

// ---------------- launch ----------------
extern "C" void kernel_launch(void* const* d_in, const int* in_sizes, int n_in,
                              void* d_out, int out_size) {
    const float* x   = (const float*)d_in[0];
    const int*   ei  = (const int*)d_in[1];
    const int*   src = ei;
    const int*   dst = ei + NE;
    const float *w0 = (const float*)d_in[2],  *b0 = (const float*)d_in[3];
    const float *g0 = (const float*)d_in[4],  *bb0 = (const float*)d_in[5];
    const float *lw0 = (const float*)d_in[6], *lb0 = (const float*)d_in[7];
    const float *w1 = (const float*)d_in[8],  *b1 = (const float*)d_in[9];
    const float *g1 = (const float*)d_in[10], *bb1 = (const float*)d_in[11];
    const float *lw1 = (const float*)d_in[12], *lb1 = (const float*)d_in[13];
    const float *w2 = (const float*)d_in[14], *b2 = (const float*)d_in[15];
    const float *g2 = (const float*)d_in[16], *bb2 = (const float*)d_in[17];
    const float *lw2 = (const float*)d_in[18], *lb2 = (const float*)d_in[19];
    float* out = (float*)d_out;

    // build (+ weight transposes in block 0)
    k_zero<<<NBLK_N, 256>>>(w1, w2);
    k_fill<<<(NE / 4 + 255) / 256, 256>>>(src, dst);
    k_dinvx<<<NBLK_N, 256>>>(x);

    // stage 0 (y never materialized: stats in k_mmred, recompute in k_postmm)
    k_agg4t2<0><<<NBLK_N2, 256>>>(nullptr, nullptr, nullptr);         // g_xs -> g_z4
    k_mmred<<<256, 256>>>(w0, b0, g0, bb0);                           // stats only
    k_postmm<3, 1, 64, true><<<(NN + 127) / 128, 128>>>(lw0, lb0, w0, b0);  // -> g_hh

    // stage 1
    k_agg64<<<AGG_BLK, 256>>>(b1);                                    // -> g_y + g_bp
    k_finstats<<<256, 256>>>(g1, bb1);                                // g_bp -> scale/shift
    k_postmm<5, 2, 3, false><<<(NN + 127) / 128, 128>>>(lw1, lb1, nullptr, nullptr); // -> g_h

    // stage 2 (fused BN stats, proven in R15)
    k_agg4t2<1><<<NBLK_N2, 256>>>(b2, g2, bb2);                       // -> g_y[N,3] + scale/shift
    k_post3<<<NBLK_N, 256>>>(lw2, lb2, out);
}